// round 11
// baseline (speedup 1.0000x reference)
#include <cuda_runtime.h>
#include <cuda_fp16.h>
#include <stdint.h>

// ---------------------------------------------------------------------------
// HashEncoder (Instant-NGP multires hash grid): B=2097152 pts, D=3, L=16, C=2
// base_res=16, desired=2048, log2_hashmap=19.
//
// res : 16 23 31 43 59 | 81 112 154 213 295 407 562 777 1073 1483 2048
// l<5 dense (res^3 aligned to 8), l>=5 hashed with hmap = 2^19.
//
// R9: persistent CTAs (grid = #SMs, 1024 thr) cache dense levels 0-2
// (46056 fp16x2 entries = 184 KB) in shared memory -> their 12 lane-loads per
// point leave the L1tex global-wavefront queue (the measured binder,
// ~1 cyc/lane) and drain on the smem crossbar instead. Levels 3-4 use the
// gmem dup-pair table (1 aligned 8B load per x-pair); hash levels use the
// fp16x2 shadow with the paired-duo trick (~50% one 8B load, else two 4B).
// Gmem lane-loads/point: 86 -> 74.
// ---------------------------------------------------------------------------

#define NLEV 16
#define TPB 1024
#define PTS_PER_TILE 128          // TPB / 8 subthreads
#define TOTAL_PARAMS 6098120
#define DENSE_PARAMS 330952       // OFFSETS[5]
#define SMEM_ENTRIES 46056        // OFFSETS[3]: levels 0-2 entry count

__constant__ uint32_t c_res[NLEV] = {
    16u, 23u, 31u, 43u, 59u, 81u, 112u, 154u,
    213u, 295u, 407u, 562u, 777u, 1073u, 1483u, 2048u
};
__constant__ uint32_t c_off[NLEV] = {
    0u, 4096u, 16264u, 46056u, 125568u, 330952u, 855240u, 1379528u,
    1903816u, 2428104u, 2952392u, 3476680u, 4000968u, 4525256u, 5049544u, 5573832u
};

__device__ float g_scales[NLEV];
// fp16x2 shadow of the whole embedding table (one uint32 per entry), 24.4 MB.
__device__ __align__(128) uint32_t g_half[TOTAL_PARAMS];
// Duplicated pair table for dense levels: g_dup[i] = (h[i], h[i+1]).
__device__ __align__(128) unsigned long long g_dup[DENSE_PARAMS];

__global__ __launch_bounds__(256)
void convert_kernel(const float4* __restrict__ emb4) {
    if (blockIdx.x == 0 && threadIdx.x < NLEV) {
        double s = exp2((double)threadIdx.x * (7.0 / 15.0)) * 16.0 - 1.0;
        g_scales[threadIdx.x] = (float)s;
    }
    int i = blockIdx.x * blockDim.x + threadIdx.x;   // pair index
    if (i < TOTAL_PARAMS / 2) {
        float4 e = emb4[i];                          // entries 2i, 2i+1
        __half2 h0 = __floats2half2_rn(e.x, e.y);
        __half2 h1 = __floats2half2_rn(e.z, e.w);
        uint32_t w0 = *(uint32_t*)&h0;
        uint32_t w1 = *(uint32_t*)&h1;
        *(uint64_t*)&g_half[2 * i] = ((uint64_t)w1 << 32) | w0;
    }
}

__global__ __launch_bounds__(256)
void dense_dup_kernel(const float2* __restrict__ emb) {
    int i = blockIdx.x * blockDim.x + threadIdx.x;
    if (i < DENSE_PARAMS) {
        float2 e0 = emb[i];
        float2 e1 = emb[i + 1];   // in-bounds: DENSE_PARAMS < TOTAL_PARAMS
        __half2 h0 = __floats2half2_rn(e0.x, e0.y);
        __half2 h1 = __floats2half2_rn(e1.x, e1.y);
        uint32_t w0 = *(uint32_t*)&h0;
        uint32_t w1 = *(uint32_t*)&h1;
        g_dup[i] = ((unsigned long long)w1 << 32) | w0;
    }
}

// Hash-level pair-gather: if b == a^1 (~50%), one aligned 8B load fetches both
// corners; else two 4B loads. True predication, outputs pre-zeroed.
__device__ __forceinline__ void pair_gather(const uint32_t* __restrict__ tabh,
                                            uint32_t a, uint32_t b,
                                            float2& ea, float2& eb)
{
    const unsigned pr = (b == (a ^ 1u)) ? 1u : 0u;
    const uint32_t* ph = tabh + (a & ~1u);
    const uint32_t* pa = tabh + a;
    const uint32_t* pb = tabh + b;
    unsigned long long hp;
    uint32_t ua, ub;
    asm volatile(
        "{\n\t"
        ".reg .pred p;\n\t"
        "setp.ne.u32 p, %3, 0;\n\t"
        "mov.u64 %0, 0;\n\t"
        "mov.u32 %1, 0;\n\t"
        "mov.u32 %2, 0;\n\t"
        "@p  ld.global.nc.u64 %0, [%4];\n\t"
        "@!p ld.global.nc.u32 %1, [%5];\n\t"
        "@!p ld.global.nc.u32 %2, [%6];\n\t"
        "}"
        : "=l"(hp), "=r"(ua), "=r"(ub)
        : "r"(pr), "l"(ph), "l"(pa), "l"(pb));
    uint32_t wa, wb;
    if (pr) {
        const uint32_t lo = (uint32_t)hp;
        const uint32_t hi = (uint32_t)(hp >> 32);
        const bool odd = (a & 1u) != 0u;
        wa = odd ? hi : lo;
        wb = odd ? lo : hi;
    } else {
        wa = ua;
        wb = ub;
    }
    ea = __half22float2(*(const __half2*)&wa);
    eb = __half22float2(*(const __half2*)&wb);
}

// One level's interpolation. cls: 0 = smem dense (levels 0-2),
// 1 = gmem dense dup (levels 3-4), 2 = hash (levels 5-15).
__device__ __forceinline__ float2 do_level(
    int cls, float scale, uint32_t res,
    const uint32_t* __restrict__ stab,               // smem, level-offset
    const unsigned long long* __restrict__ dup,      // gmem dup, level-offset
    const uint32_t* __restrict__ tabh,               // gmem hash, level-offset
    float x, float y, float z)
{
    // pos = x*scale + 0.5, NO fma contraction (floor must match reference).
    const float posx = __fadd_rn(__fmul_rn(x, scale), 0.5f);
    const float posy = __fadd_rn(__fmul_rn(y, scale), 0.5f);
    const float posz = __fadd_rn(__fmul_rn(z, scale), 0.5f);
    const float fx = floorf(posx), fy = floorf(posy), fz = floorf(posz);
    const float tx = posx - fx,  ty = posy - fy,  tz = posz - fz;
    const uint32_t gx = (uint32_t)fx, gy = (uint32_t)fy, gz = (uint32_t)fz;
    const uint32_t rm1 = res - 1u;
    const uint32_t x0 = min(gx,      rm1), x1 = min(gx + 1u, rm1);
    const uint32_t y0 = min(gy,      rm1), y1 = min(gy + 1u, rm1);
    const uint32_t z0 = min(gz,      rm1), z1 = min(gz + 1u, rm1);

    float2 ea[4], eb[4];
    if (cls == 2) {
        const uint32_t hy0 = y0 * 2654435761u, hy1 = y1 * 2654435761u;
        const uint32_t hz0 = z0 * 805459861u,  hz1 = z1 * 805459861u;
        const uint32_t m = 0x7FFFFu;
        uint32_t ia[4], ib[4];
        ia[0] = (x0 ^ hy0 ^ hz0) & m;  ib[0] = (x1 ^ hy0 ^ hz0) & m;
        ia[1] = (x0 ^ hy1 ^ hz0) & m;  ib[1] = (x1 ^ hy1 ^ hz0) & m;
        ia[2] = (x0 ^ hy0 ^ hz1) & m;  ib[2] = (x1 ^ hy0 ^ hz1) & m;
        ia[3] = (x0 ^ hy1 ^ hz1) & m;  ib[3] = (x1 ^ hy1 ^ hz1) & m;
        #pragma unroll
        for (int q = 0; q < 4; ++q)
            pair_gather(tabh, ia[q], ib[q], ea[q], eb[q]);
    } else {
        const uint32_t r2  = res * res;
        const uint32_t by0 = y0 * res, by1 = y1 * res;
        const uint32_t bz0 = z0 * r2,  bz1 = z1 * r2;
        const uint32_t dx = (x1 == x0) ? 0u : 1u;
        uint32_t ia[4];
        ia[0] = x0 + by0 + bz0;
        ia[1] = x0 + by1 + bz0;
        ia[2] = x0 + by0 + bz1;
        ia[3] = x0 + by1 + bz1;
        if (cls == 0) {
            // smem: two 4B LDS per pair (crossbar, off the L1tex global path)
            #pragma unroll
            for (int q = 0; q < 4; ++q) {
                const uint32_t wa = stab[ia[q]];
                const uint32_t wb = stab[ia[q] + dx];
                ea[q] = __half22float2(*(const __half2*)&wa);
                eb[q] = __half22float2(*(const __half2*)&wb);
            }
        } else {
            // gmem dup: one aligned 8B load per pair
            #pragma unroll
            for (int q = 0; q < 4; ++q) {
                const unsigned long long v = __ldg(dup + ia[q]);
                const uint32_t lo = (uint32_t)v;
                const uint32_t hi = (uint32_t)(v >> 32);
                const uint32_t wb = dx ? hi : lo;
                ea[q] = __half22float2(*(const __half2*)&lo);
                eb[q] = __half22float2(*(const __half2*)&wb);
            }
        }
    }

    const float wx0 = 1.0f - tx, wy0 = 1.0f - ty, wz0 = 1.0f - tz;
    float a0 = 0.0f, a1 = 0.0f;
    #pragma unroll
    for (int q = 0; q < 4; ++q) {
        const float wy = (q & 1) ? ty : wy0;
        const float wz = (q & 2) ? tz : wz0;
        const float wyz = __fmul_rn(wy, wz);
        const float wa  = __fmul_rn(wx0, wyz);
        const float wb  = __fmul_rn(tx,  wyz);
        a0 = fmaf(wa, ea[q].x, a0);
        a1 = fmaf(wa, ea[q].y, a1);
        a0 = fmaf(wb, eb[q].x, a0);
        a1 = fmaf(wb, eb[q].y, a1);
    }
    return make_float2(a0, a1);
}

__global__ __launch_bounds__(TPB, 1)
void hash_encode_kernel(const float* __restrict__ inputs,
                        float4* __restrict__ out,
                        int npts, int ntiles)
{
    extern __shared__ uint32_t dsm[];
    uint32_t* s_tab = dsm;                       // 46056 * 4 = 184224 B
    float*    s_in  = (float*)(dsm + SMEM_ENTRIES);  // 128*3 floats

    // Fill smem cache of levels 0-2 (coalesced, once per CTA).
    for (int i = threadIdx.x; i < SMEM_ENTRIES; i += TPB)
        s_tab[i] = g_half[i];

    const int tid = threadIdx.x;
    const int pl  = tid >> 3;     // point-lane within tile (0..127)
    const int s   = tid & 7;      // sub-thread: levels 2s, 2s+1
    const int l0 = 2 * s, l1 = 2 * s + 1;

    // Per-thread level params, fixed across tiles.
    const float sc0 = g_scales[l0],  sc1 = g_scales[l1];
    const uint32_t res0 = c_res[l0], res1 = c_res[l1];
    const uint32_t off0 = c_off[l0], off1 = c_off[l1];
    const int cls0 = (l0 >= 5) ? 2 : (l0 >= 3 ? 1 : 0);
    const int cls1 = (l1 >= 5) ? 2 : (l1 >= 3 ? 1 : 0);
    const uint32_t* st0 = s_tab + off0;
    const uint32_t* st1 = s_tab + off1;
    const unsigned long long* dp0 = g_dup + off0;
    const unsigned long long* dp1 = g_dup + off1;
    const uint32_t* th0 = g_half + off0;
    const uint32_t* th1 = g_half + off1;

    for (int tile = blockIdx.x; tile < ntiles; tile += gridDim.x) {
        __syncthreads();   // protect s_in from previous iteration's readers
        if (tid < PTS_PER_TILE * 3) {
            int gi = tile * (PTS_PER_TILE * 3) + tid;
            if (gi < npts * 3) s_in[tid] = inputs[gi];
        }
        __syncthreads();

        const int point = tile * PTS_PER_TILE + pl;
        if (point >= npts) continue;

        const float x = s_in[pl * 3 + 0];
        const float y = s_in[pl * 3 + 1];
        const float z = s_in[pl * 3 + 2];

        const float2 rA = do_level(cls0, sc0, res0, st0, dp0, th0, x, y, z);
        const float2 rB = do_level(cls1, sc1, res1, st1, dp1, th1, x, y, z);

        // Warp = 4 points x 8 subthreads -> 512B contiguous, fully coalesced.
        out[point * 8 + s] = make_float4(rA.x, rA.y, rB.x, rB.y);
    }
}

extern "C" void kernel_launch(void* const* d_in, const int* in_sizes, int n_in,
                              void* d_out, int out_size)
{
    const float*  inputs = (const float*)d_in[0];
    const float2* emb    = (const float2*)d_in[1];
    float4*       out    = (float4*)d_out;

    const int npts = in_sizes[0] / 3;

    const int npairs = TOTAL_PARAMS / 2;
    convert_kernel<<<(npairs + 255) / 256, 256>>>((const float4*)emb);
    dense_dup_kernel<<<(DENSE_PARAMS + 255) / 256, 256>>>(emb);

    static int smem_set = 0;
    const int smem_bytes = SMEM_ENTRIES * 4 + PTS_PER_TILE * 3 * 4 + 16;
    if (!smem_set) {
        cudaFuncSetAttribute(hash_encode_kernel,
                             cudaFuncAttributeMaxDynamicSharedMemorySize,
                             smem_bytes);
        smem_set = 1;
    }

    int nsm = 148;
    cudaDeviceGetAttribute(&nsm, cudaDevAttrMultiProcessorCount, 0);

    const int ntiles = (npts + PTS_PER_TILE - 1) / PTS_PER_TILE;
    hash_encode_kernel<<<nsm, TPB, smem_bytes>>>(inputs, out, npts, ntiles);
}

// round 12
// speedup vs baseline: 1.0577x; 1.0577x over previous
#include <cuda_runtime.h>
#include <cuda_fp16.h>
#include <stdint.h>

// ---------------------------------------------------------------------------
// HashEncoder (Instant-NGP multires hash grid): B=2097152 pts, D=3, L=16, C=2
// base_res=16, desired=2048, log2_hashmap=19.
//
// res : 16 23 31 43 59 | 81 112 154 213 295 407 562 777 1073 1483 2048
// l<5 dense (res^3 aligned to 8), l>=5 hashed with hmap = 2^19.
//
// R10 = R8 structure (best, 522us) + two changes:
//  * hash-level gathers use ld.global.cg (L2-cached, L1-BYPASS): the 23MB
//    hash stream never hits L1, so its line fills only burned L1TEX bandwidth
//    and evicted the dense dup entries. (.cg keeps L2 allocation — unlike
//    L1::no_allocate, which killed L2 residency in R6.)
//  * single setup kernel; g_half converted only for the hash region.
// Lane-loads/point: hash 11*6 avg + dense 5*4 = 86 (the measured binder is
// ~1 wavefront per scattered lane-load on the unified L1TEX pipe).
// R9 lesson: LDS shares the L1TEX pipe -> smem caching cannot help here.
// ---------------------------------------------------------------------------

#define NLEV 16
#define BLOCK 256
#define PTS_PER_BLK 32            // 8 threads per point, 2 levels per thread
#define TOTAL_PARAMS 6098120
#define DENSE_PARAMS 330952       // OFFSETS[5]
#define HASH_PARAMS (TOTAL_PARAMS - DENSE_PARAMS)   // 5767168, even

__constant__ uint32_t c_res[NLEV] = {
    16u, 23u, 31u, 43u, 59u, 81u, 112u, 154u,
    213u, 295u, 407u, 562u, 777u, 1073u, 1483u, 2048u
};
__constant__ uint32_t c_off[NLEV] = {
    0u, 4096u, 16264u, 46056u, 125568u, 330952u, 855240u, 1379528u,
    1903816u, 2428104u, 2952392u, 3476680u, 4000968u, 4525256u, 5049544u, 5573832u
};

__device__ float g_scales[NLEV];
// fp16x2 shadow of the embedding table (one uint32 per entry). Only the hash
// region [DENSE_PARAMS, TOTAL_PARAMS) is ever read; indexing stays global.
__device__ __align__(128) uint32_t g_half[TOTAL_PARAMS];
// Duplicated pair table for dense levels: g_dup[i] = (h[i], h[i+1]).
__device__ __align__(128) unsigned long long g_dup[DENSE_PARAMS];

// One setup kernel: dense dup pairs + hash fp16 shadow + scales.
__global__ __launch_bounds__(256)
void setup_kernel(const float2* __restrict__ emb) {
    if (blockIdx.x == 0 && threadIdx.x < NLEV) {
        double s = exp2((double)threadIdx.x * (7.0 / 15.0)) * 16.0 - 1.0;
        g_scales[threadIdx.x] = (float)s;
    }
    const int gi = blockIdx.x * blockDim.x + threadIdx.x;
    // Dense dup: one 8B entry per dense index.
    if (gi < DENSE_PARAMS) {
        float2 e0 = emb[gi];
        float2 e1 = emb[gi + 1];          // in-bounds (< TOTAL_PARAMS)
        __half2 h0 = __floats2half2_rn(e0.x, e0.y);
        __half2 h1 = __floats2half2_rn(e1.x, e1.y);
        uint32_t w0 = *(uint32_t*)&h0;
        uint32_t w1 = *(uint32_t*)&h1;
        g_dup[gi] = ((unsigned long long)w1 << 32) | w0;
    }
    // Hash region fp16 shadow: pair i covers entries DENSE_PARAMS + 2i, +2i+1.
    if (gi < HASH_PARAMS / 2) {
        const int base = DENSE_PARAMS + 2 * gi;
        const float4 e = *(const float4*)(emb + base);
        __half2 h0 = __floats2half2_rn(e.x, e.y);
        __half2 h1 = __floats2half2_rn(e.z, e.w);
        uint32_t w0 = *(uint32_t*)&h0;
        uint32_t w1 = *(uint32_t*)&h1;
        *(uint64_t*)&g_half[base] = ((uint64_t)w1 << 32) | w0;
    }
}

// Hash-level pair-gather, L1-bypassed (.cg = cache at L2 only): if b == a^1
// (~50%), one aligned 8B load fetches both corners; else two 4B loads.
__device__ __forceinline__ void pair_gather(const uint32_t* __restrict__ tabh,
                                            uint32_t a, uint32_t b,
                                            float2& ea, float2& eb)
{
    const unsigned pr = (b == (a ^ 1u)) ? 1u : 0u;
    const uint32_t* ph = tabh + (a & ~1u);   // 8B-aligned (offsets all even)
    const uint32_t* pa = tabh + a;
    const uint32_t* pb = tabh + b;
    unsigned long long hp;
    uint32_t ua, ub;
    asm volatile(
        "{\n\t"
        ".reg .pred p;\n\t"
        "setp.ne.u32 p, %3, 0;\n\t"
        "mov.u64 %0, 0;\n\t"
        "mov.u32 %1, 0;\n\t"
        "mov.u32 %2, 0;\n\t"
        "@p  ld.global.cg.u64 %0, [%4];\n\t"
        "@!p ld.global.cg.u32 %1, [%5];\n\t"
        "@!p ld.global.cg.u32 %2, [%6];\n\t"
        "}"
        : "=l"(hp), "=r"(ua), "=r"(ub)
        : "r"(pr), "l"(ph), "l"(pa), "l"(pb));
    uint32_t wa, wb;
    if (pr) {
        const uint32_t lo = (uint32_t)hp;          // entry a&~1 (even)
        const uint32_t hi = (uint32_t)(hp >> 32);  // entry a|1  (odd)
        const bool odd = (a & 1u) != 0u;
        wa = odd ? hi : lo;
        wb = odd ? lo : hi;
    } else {
        wa = ua;
        wb = ub;
    }
    ea = __half22float2(*(const __half2*)&wa);
    eb = __half22float2(*(const __half2*)&wb);
}

__global__ __launch_bounds__(BLOCK)
void hash_encode_kernel(const float* __restrict__ inputs,
                        float4* __restrict__ out,
                        int npts)
{
    __shared__ float s_in[PTS_PER_BLK * 3];
    __shared__ float s_scale[NLEV];

    const int tid = threadIdx.x;
    {
        int gidx = blockIdx.x * (PTS_PER_BLK * 3) + tid;
        if (tid < PTS_PER_BLK * 3 && gidx < npts * 3)
            s_in[tid] = inputs[gidx];
        if (tid < NLEV)
            s_scale[tid] = g_scales[tid];
    }
    __syncthreads();

    const int p = tid >> 3;       // point within block (0..31)
    const int s = tid & 7;        // sub-thread: handles levels 2s, 2s+1
    const long long point = (long long)blockIdx.x * PTS_PER_BLK + p;
    if (point >= npts) return;

    const float x = s_in[p * 3 + 0];
    const float y = s_in[p * 3 + 1];
    const float z = s_in[p * 3 + 2];

    float4 r;

    #pragma unroll
    for (int i = 0; i < 2; ++i) {
        const int l = (s << 1) + i;
        const float scale  = s_scale[l];
        const uint32_t res = c_res[l];

        // pos = x*scale + 0.5, NO fma contraction (floor must match reference).
        const float posx = __fadd_rn(__fmul_rn(x, scale), 0.5f);
        const float posy = __fadd_rn(__fmul_rn(y, scale), 0.5f);
        const float posz = __fadd_rn(__fmul_rn(z, scale), 0.5f);
        const float fx = floorf(posx), fy = floorf(posy), fz = floorf(posz);
        const float tx = posx - fx,  ty = posy - fy,  tz = posz - fz;
        const uint32_t gx = (uint32_t)fx, gy = (uint32_t)fy, gz = (uint32_t)fz;
        const uint32_t rm1 = res - 1u;
        const uint32_t x0 = min(gx,      rm1), x1 = min(gx + 1u, rm1);
        const uint32_t y0 = min(gy,      rm1), y1 = min(gy + 1u, rm1);
        const uint32_t z0 = min(gz,      rm1), z1 = min(gz + 1u, rm1);

        // 4 x-pairs; pair q has (y,z) bits (q&1, q>>1).
        float2 ea[4], eb[4];
        if (l >= 5) {
            const uint32_t* __restrict__ tabh = g_half + c_off[l];
            const uint32_t hy0 = y0 * 2654435761u, hy1 = y1 * 2654435761u;
            const uint32_t hz0 = z0 * 805459861u,  hz1 = z1 * 805459861u;
            const uint32_t m = 0x7FFFFu;
            uint32_t ia[4], ib[4];
            ia[0] = (x0 ^ hy0 ^ hz0) & m;  ib[0] = (x1 ^ hy0 ^ hz0) & m;
            ia[1] = (x0 ^ hy1 ^ hz0) & m;  ib[1] = (x1 ^ hy1 ^ hz0) & m;
            ia[2] = (x0 ^ hy0 ^ hz1) & m;  ib[2] = (x1 ^ hy0 ^ hz1) & m;
            ia[3] = (x0 ^ hy1 ^ hz1) & m;  ib[3] = (x1 ^ hy1 ^ hz1) & m;
            #pragma unroll
            for (int q = 0; q < 4; ++q)
                pair_gather(tabh, ia[q], ib[q], ea[q], eb[q]);
        } else {
            // Dense: dup table makes every x-pair exactly one aligned 8B load.
            const unsigned long long* __restrict__ dup = g_dup + c_off[l];
            const bool bsame = (x1 == x0);
            const uint32_t r2  = res * res;
            const uint32_t by0 = y0 * res, by1 = y1 * res;
            const uint32_t bz0 = z0 * r2,  bz1 = z1 * r2;
            uint32_t ia[4];
            ia[0] = x0 + by0 + bz0;
            ia[1] = x0 + by1 + bz0;
            ia[2] = x0 + by0 + bz1;
            ia[3] = x0 + by1 + bz1;
            #pragma unroll
            for (int q = 0; q < 4; ++q) {
                const unsigned long long v = __ldg(dup + ia[q]);
                const uint32_t lo = (uint32_t)v;           // entry ia
                const uint32_t hi = (uint32_t)(v >> 32);   // entry ia+1
                const uint32_t wb = bsame ? lo : hi;
                ea[q] = __half22float2(*(const __half2*)&lo);
                eb[q] = __half22float2(*(const __half2*)&wb);
            }
        }

        const float wx0 = 1.0f - tx, wy0 = 1.0f - ty, wz0 = 1.0f - tz;
        float a0 = 0.0f, a1 = 0.0f;
        #pragma unroll
        for (int q = 0; q < 4; ++q) {
            const float wy = (q & 1) ? ty : wy0;
            const float wz = (q & 2) ? tz : wz0;
            const float wyz = __fmul_rn(wy, wz);
            const float wa  = __fmul_rn(wx0, wyz);
            const float wb  = __fmul_rn(tx,  wyz);
            a0 = fmaf(wa, ea[q].x, a0);
            a1 = fmaf(wa, ea[q].y, a1);
            a0 = fmaf(wb, eb[q].x, a0);
            a1 = fmaf(wb, eb[q].y, a1);
        }
        if (i == 0) { r.x = a0; r.y = a1; }
        else        { r.z = a0; r.w = a1; }
    }

    // Warp = 4 points x 8 subthreads -> 512B contiguous store, fully coalesced.
    out[point * 8 + s] = r;
}

extern "C" void kernel_launch(void* const* d_in, const int* in_sizes, int n_in,
                              void* d_out, int out_size)
{
    const float*  inputs = (const float*)d_in[0];
    const float2* emb    = (const float2*)d_in[1];
    float4*       out    = (float4*)d_out;

    const int npts = in_sizes[0] / 3;

    // One setup launch: max(DENSE_PARAMS, HASH_PARAMS/2) threads needed.
    const int setup_n = (HASH_PARAMS / 2 > DENSE_PARAMS) ? HASH_PARAMS / 2
                                                         : DENSE_PARAMS;
    setup_kernel<<<(setup_n + 255) / 256, 256>>>(emb);

    const int total_threads = npts * 8;
    const int nblocks = (total_threads + BLOCK - 1) / BLOCK;
    hash_encode_kernel<<<nblocks, BLOCK>>>(inputs, out, npts);
}

// round 13
// speedup vs baseline: 1.2178x; 1.1513x over previous
#include <cuda_runtime.h>
#include <cuda_fp16.h>
#include <stdint.h>

// ---------------------------------------------------------------------------
// HashEncoder (Instant-NGP multires hash grid): B=2097152 pts, D=3, L=16, C=2
// base_res=16, desired=2048, log2_hashmap=19.
//
// res : 16 23 31 43 59 | 81 112 154 213 295 407 562 777 1073 1483 2048
// l<5 dense (res^3 aligned to 8), l>=5 hashed with hmap = 2^19 (each hash
// level is exactly 2^19 entries).
//
// R11 = R8 (best, 522us: plain ld.global.nc fp16 gathers — R10 showed L1
// bypass loses real L1 hits) + d=3 XOR-shadow table:
//   hash pair relation ia^ib = x0^x1: d=1 (x0 even, 50%) -> aligned duo in
//   g_half, 1x8B. d=3 (x0=1 mod 4, 25%) -> g_d3[A]=(h[A],h[A^3]), 1x8B.
//   else -> two 4B loads. Hash loads/level avg 6 -> 5.
// Dense levels: dup table, every x-pair one 8B load.
// Lane-loads/point: 86 -> 75 (binder = scattered lane-loads on L1TEX).
// ---------------------------------------------------------------------------

#define NLEV 16
#define BLOCK 256
#define PTS_PER_BLK 32            // 8 threads per point, 2 levels per thread
#define TOTAL_PARAMS 6098120
#define DENSE_PARAMS 330952       // OFFSETS[5]
#define HASH_PARAMS (TOTAL_PARAMS - DENSE_PARAMS)   // 11 * 2^19 = 5767168
#define HMASK 0x7FFFFu

__constant__ uint32_t c_res[NLEV] = {
    16u, 23u, 31u, 43u, 59u, 81u, 112u, 154u,
    213u, 295u, 407u, 562u, 777u, 1073u, 1483u, 2048u
};
__constant__ uint32_t c_off[NLEV] = {
    0u, 4096u, 16264u, 46056u, 125568u, 330952u, 855240u, 1379528u,
    1903816u, 2428104u, 2952392u, 3476680u, 4000968u, 4525256u, 5049544u, 5573832u
};

__device__ float g_scales[NLEV];
// fp16x2 shadow (one uint32 per entry); only hash region is read from here.
__device__ __align__(128) uint32_t g_half[TOTAL_PARAMS];
// Dense dup pairs: g_dup[i] = (h[i], h[i+1]).
__device__ __align__(128) unsigned long long g_dup[DENSE_PARAMS];
// Hash d=3 shadow, level-major: g_d3[(lvl<<19)|i] = (h[i], h[i^3]) (level-local).
__device__ __align__(128) unsigned long long g_d3[HASH_PARAMS];

// One setup kernel: scales + dense dup + hash fp16 shadow + d3 shadow.
__global__ __launch_bounds__(256)
void setup_kernel(const float2* __restrict__ emb) {
    if (blockIdx.x == 0 && threadIdx.x < NLEV) {
        double s = exp2((double)threadIdx.x * (7.0 / 15.0)) * 16.0 - 1.0;
        g_scales[threadIdx.x] = (float)s;
    }
    const int gi = blockIdx.x * blockDim.x + threadIdx.x;
    if (gi < DENSE_PARAMS) {
        float2 e0 = emb[gi];
        float2 e1 = emb[gi + 1];          // in-bounds (< TOTAL_PARAMS)
        __half2 h0 = __floats2half2_rn(e0.x, e0.y);
        __half2 h1 = __floats2half2_rn(e1.x, e1.y);
        uint32_t w0 = *(uint32_t*)&h0;
        uint32_t w1 = *(uint32_t*)&h1;
        g_dup[gi] = ((unsigned long long)w1 << 32) | w0;
    }
    if (gi < HASH_PARAMS) {
        const int j  = DENSE_PARAMS + gi;      // global entry index
        const int li = gi & (int)HMASK;        // level-local index
        const int jb = j - li;                 // level base (global)
        float2 e  = emb[j];
        float2 e3 = emb[jb + (li ^ 3)];        // li^3 < 2^19: in-level
        __half2 h  = __floats2half2_rn(e.x,  e.y);
        __half2 h3 = __floats2half2_rn(e3.x, e3.y);
        uint32_t w  = *(uint32_t*)&h;
        uint32_t w3 = *(uint32_t*)&h3;
        g_half[j] = w;
        g_d3[gi]  = ((unsigned long long)w3 << 32) | w;   // (h[li], h[li^3])
    }
}

// Hash-level pair-gather, 3-way: d = a^b.
//   d==1 -> one aligned 8B duo from g_half (entries a&~1, a|1)
//   d==3 -> one 8B load from g_d3[a] = (h[a], h[a^3])
//   else -> two 4B loads (covers d>=7 and the clamp case a==b).
__device__ __forceinline__ void pair_gather_h(
    const uint32_t* __restrict__ tabh,
    const unsigned long long* __restrict__ d3l,
    uint32_t a, uint32_t b, float2& ea, float2& eb)
{
    const uint32_t d = a ^ b;
    const unsigned pr1 = (d == 1u) ? 1u : 0u;
    const unsigned pr3 = (d == 3u) ? 1u : 0u;
    const unsigned prn = (pr1 | pr3) ^ 1u;
    const uint32_t* pduo = tabh + (a & ~1u);
    const unsigned long long* pd3 = d3l + a;   // 8*a: 8B-aligned
    const uint32_t* pa = tabh + a;
    const uint32_t* pb = tabh + b;
    unsigned long long duo, dv;
    uint32_t ua, ub;
    asm volatile(
        "{\n\t"
        ".reg .pred p1, p3, pn;\n\t"
        "setp.ne.u32 p1, %4, 0;\n\t"
        "setp.ne.u32 p3, %5, 0;\n\t"
        "setp.ne.u32 pn, %6, 0;\n\t"
        "mov.u64 %0, 0;\n\t"
        "mov.u64 %1, 0;\n\t"
        "mov.u32 %2, 0;\n\t"
        "mov.u32 %3, 0;\n\t"
        "@p1 ld.global.nc.u64 %0, [%7];\n\t"
        "@p3 ld.global.nc.u64 %1, [%8];\n\t"
        "@pn ld.global.nc.u32 %2, [%9];\n\t"
        "@pn ld.global.nc.u32 %3, [%10];\n\t"
        "}"
        : "=l"(duo), "=l"(dv), "=r"(ua), "=r"(ub)
        : "r"(pr1), "r"(pr3), "r"(prn),
          "l"(pduo), "l"(pd3), "l"(pa), "l"(pb));
    const uint32_t dlo = (uint32_t)duo, dhi = (uint32_t)(duo >> 32);
    const uint32_t tlo = (uint32_t)dv,  thi = (uint32_t)(dv >> 32);
    uint32_t wa, wb;
    if (pr1) {
        const bool odd = (a & 1u) != 0u;
        wa = odd ? dhi : dlo;
        wb = odd ? dlo : dhi;
    } else if (pr3) {
        wa = tlo;  wb = thi;
    } else {
        wa = ua;   wb = ub;
    }
    ea = __half22float2(*(const __half2*)&wa);
    eb = __half22float2(*(const __half2*)&wb);
}

__global__ __launch_bounds__(BLOCK)
void hash_encode_kernel(const float* __restrict__ inputs,
                        float4* __restrict__ out,
                        int npts)
{
    __shared__ float s_in[PTS_PER_BLK * 3];
    __shared__ float s_scale[NLEV];

    const int tid = threadIdx.x;
    {
        int gidx = blockIdx.x * (PTS_PER_BLK * 3) + tid;
        if (tid < PTS_PER_BLK * 3 && gidx < npts * 3)
            s_in[tid] = inputs[gidx];
        if (tid < NLEV)
            s_scale[tid] = g_scales[tid];
    }
    __syncthreads();

    const int p = tid >> 3;       // point within block (0..31)
    const int s = tid & 7;        // sub-thread: handles levels 2s, 2s+1
    const long long point = (long long)blockIdx.x * PTS_PER_BLK + p;
    if (point >= npts) return;

    const float x = s_in[p * 3 + 0];
    const float y = s_in[p * 3 + 1];
    const float z = s_in[p * 3 + 2];

    float4 r;

    #pragma unroll
    for (int i = 0; i < 2; ++i) {
        const int l = (s << 1) + i;
        const float scale  = s_scale[l];
        const uint32_t res = c_res[l];

        // pos = x*scale + 0.5, NO fma contraction (floor must match reference).
        const float posx = __fadd_rn(__fmul_rn(x, scale), 0.5f);
        const float posy = __fadd_rn(__fmul_rn(y, scale), 0.5f);
        const float posz = __fadd_rn(__fmul_rn(z, scale), 0.5f);
        const float fx = floorf(posx), fy = floorf(posy), fz = floorf(posz);
        const float tx = posx - fx,  ty = posy - fy,  tz = posz - fz;
        const uint32_t gx = (uint32_t)fx, gy = (uint32_t)fy, gz = (uint32_t)fz;
        const uint32_t rm1 = res - 1u;
        const uint32_t x0 = min(gx,      rm1), x1 = min(gx + 1u, rm1);
        const uint32_t y0 = min(gy,      rm1), y1 = min(gy + 1u, rm1);
        const uint32_t z0 = min(gz,      rm1), z1 = min(gz + 1u, rm1);

        // 4 x-pairs; pair q has (y,z) bits (q&1, q>>1).
        float2 ea[4], eb[4];
        if (l >= 5) {
            const uint32_t* __restrict__ tabh = g_half + c_off[l];
            const unsigned long long* __restrict__ d3l =
                g_d3 + ((uint32_t)(l - 5) << 19);
            const uint32_t hy0 = y0 * 2654435761u, hy1 = y1 * 2654435761u;
            const uint32_t hz0 = z0 * 805459861u,  hz1 = z1 * 805459861u;
            uint32_t ia[4], ib[4];
            ia[0] = (x0 ^ hy0 ^ hz0) & HMASK;  ib[0] = (x1 ^ hy0 ^ hz0) & HMASK;
            ia[1] = (x0 ^ hy1 ^ hz0) & HMASK;  ib[1] = (x1 ^ hy1 ^ hz0) & HMASK;
            ia[2] = (x0 ^ hy0 ^ hz1) & HMASK;  ib[2] = (x1 ^ hy0 ^ hz1) & HMASK;
            ia[3] = (x0 ^ hy1 ^ hz1) & HMASK;  ib[3] = (x1 ^ hy1 ^ hz1) & HMASK;
            #pragma unroll
            for (int q = 0; q < 4; ++q)
                pair_gather_h(tabh, d3l, ia[q], ib[q], ea[q], eb[q]);
        } else {
            // Dense: dup table makes every x-pair exactly one aligned 8B load.
            const unsigned long long* __restrict__ dup = g_dup + c_off[l];
            const bool bsame = (x1 == x0);
            const uint32_t r2  = res * res;
            const uint32_t by0 = y0 * res, by1 = y1 * res;
            const uint32_t bz0 = z0 * r2,  bz1 = z1 * r2;
            uint32_t ia[4];
            ia[0] = x0 + by0 + bz0;
            ia[1] = x0 + by1 + bz0;
            ia[2] = x0 + by0 + bz1;
            ia[3] = x0 + by1 + bz1;
            #pragma unroll
            for (int q = 0; q < 4; ++q) {
                const unsigned long long v = __ldg(dup + ia[q]);
                const uint32_t lo = (uint32_t)v;           // entry ia
                const uint32_t hi = (uint32_t)(v >> 32);   // entry ia+1
                const uint32_t wb = bsame ? lo : hi;
                ea[q] = __half22float2(*(const __half2*)&lo);
                eb[q] = __half22float2(*(const __half2*)&wb);
            }
        }

        const float wx0 = 1.0f - tx, wy0 = 1.0f - ty, wz0 = 1.0f - tz;
        float a0 = 0.0f, a1 = 0.0f;
        #pragma unroll
        for (int q = 0; q < 4; ++q) {
            const float wy = (q & 1) ? ty : wy0;
            const float wz = (q & 2) ? tz : wz0;
            const float wyz = __fmul_rn(wy, wz);
            const float wa  = __fmul_rn(wx0, wyz);
            const float wb  = __fmul_rn(tx,  wyz);
            a0 = fmaf(wa, ea[q].x, a0);
            a1 = fmaf(wa, ea[q].y, a1);
            a0 = fmaf(wb, eb[q].x, a0);
            a1 = fmaf(wb, eb[q].y, a1);
        }
        if (i == 0) { r.x = a0; r.y = a1; }
        else        { r.z = a0; r.w = a1; }
    }

    // Warp = 4 points x 8 subthreads -> 512B contiguous store, fully coalesced.
    out[point * 8 + s] = r;
}

extern "C" void kernel_launch(void* const* d_in, const int* in_sizes, int n_in,
                              void* d_out, int out_size)
{
    const float*  inputs = (const float*)d_in[0];
    const float2* emb    = (const float2*)d_in[1];
    float4*       out    = (float4*)d_out;

    const int npts = in_sizes[0] / 3;

    setup_kernel<<<(HASH_PARAMS + 255) / 256, 256>>>(emb);

    const int total_threads = npts * 8;
    const int nblocks = (total_threads + BLOCK - 1) / BLOCK;
    hash_encode_kernel<<<nblocks, BLOCK>>>(inputs, out, npts);
}

// round 14
// speedup vs baseline: 1.2252x; 1.0061x over previous
#include <cuda_runtime.h>
#include <cuda_fp16.h>
#include <stdint.h>

// ---------------------------------------------------------------------------
// HashEncoder (Instant-NGP multires hash grid): B=2097152 pts, D=3, L=16, C=2
// base_res=16, desired=2048, log2_hashmap=19.
//
// res : 16 23 31 43 59 | 81 112 154 213 295 407 562 777 1073 1483 2048
// l<5 dense (res^3 aligned to 8), l>=5 hashed with hmap = 2^19.
//
// R12 = R8 gather structure (proven best: 86 lane-loads/pt, plain ld.global.nc
// fp16 gathers; L1 hints and L1 bypass both regress; d3 shadow table is
// L2-rent-neutral; LDS shares the L1TEX pipe so smem caching can't help)
// + single setup kernel + __launch_bounds__(256,7) for 56 warps/SM.
//   hash levels: paired x-duo (idx1==idx0^1, ~50%) = one aligned 8B load,
//                else two 4B loads.
//   dense levels: dup table g_dup[i]=(h[i],h[i+1]) -> every pair one 8B load.
// ---------------------------------------------------------------------------

#define NLEV 16
#define BLOCK 256
#define PTS_PER_BLK 32            // 8 threads per point, 2 levels per thread
#define TOTAL_PARAMS 6098120
#define DENSE_PARAMS 330952       // OFFSETS[5]
#define HASH_PARAMS (TOTAL_PARAMS - DENSE_PARAMS)   // 11 * 2^19 = 5767168

__constant__ uint32_t c_res[NLEV] = {
    16u, 23u, 31u, 43u, 59u, 81u, 112u, 154u,
    213u, 295u, 407u, 562u, 777u, 1073u, 1483u, 2048u
};
__constant__ uint32_t c_off[NLEV] = {
    0u, 4096u, 16264u, 46056u, 125568u, 330952u, 855240u, 1379528u,
    1903816u, 2428104u, 2952392u, 3476680u, 4000968u, 4525256u, 5049544u, 5573832u
};

__device__ float g_scales[NLEV];
// fp16x2 shadow (one uint32 per entry); only the hash region is read.
__device__ __align__(128) uint32_t g_half[TOTAL_PARAMS];
// Dense dup pairs: g_dup[i] = (h[i], h[i+1]).
__device__ __align__(128) unsigned long long g_dup[DENSE_PARAMS];

// One setup kernel: scales + dense dup + hash-region fp16 shadow.
__global__ __launch_bounds__(256)
void setup_kernel(const float2* __restrict__ emb) {
    if (blockIdx.x == 0 && threadIdx.x < NLEV) {
        double s = exp2((double)threadIdx.x * (7.0 / 15.0)) * 16.0 - 1.0;
        g_scales[threadIdx.x] = (float)s;
    }
    const int gi = blockIdx.x * blockDim.x + threadIdx.x;
    // Dense dup: one 8B entry per dense index.
    if (gi < DENSE_PARAMS) {
        float2 e0 = emb[gi];
        float2 e1 = emb[gi + 1];          // in-bounds (< TOTAL_PARAMS)
        __half2 h0 = __floats2half2_rn(e0.x, e0.y);
        __half2 h1 = __floats2half2_rn(e1.x, e1.y);
        uint32_t w0 = *(uint32_t*)&h0;
        uint32_t w1 = *(uint32_t*)&h1;
        g_dup[gi] = ((unsigned long long)w1 << 32) | w0;
    }
    // Hash region fp16 shadow: pair i covers entries DENSE_PARAMS+2i, +2i+1.
    if (gi < HASH_PARAMS / 2) {
        const int base = DENSE_PARAMS + 2 * gi;
        const float4 e = *(const float4*)(emb + base);
        __half2 h0 = __floats2half2_rn(e.x, e.y);
        __half2 h1 = __floats2half2_rn(e.z, e.w);
        uint32_t w0 = *(uint32_t*)&h0;
        uint32_t w1 = *(uint32_t*)&h1;
        *(uint64_t*)&g_half[base] = ((uint64_t)w1 << 32) | w0;
    }
}

// Hash-level pair-gather: if b == a^1 (~50%), one aligned 8B load fetches both
// corners; else two 4B loads. True predication, outputs pre-zeroed.
__device__ __forceinline__ void pair_gather(const uint32_t* __restrict__ tabh,
                                            uint32_t a, uint32_t b,
                                            float2& ea, float2& eb)
{
    const unsigned pr = (b == (a ^ 1u)) ? 1u : 0u;
    const uint32_t* ph = tabh + (a & ~1u);   // 8B-aligned (offsets all even)
    const uint32_t* pa = tabh + a;
    const uint32_t* pb = tabh + b;
    unsigned long long hp;
    uint32_t ua, ub;
    asm volatile(
        "{\n\t"
        ".reg .pred p;\n\t"
        "setp.ne.u32 p, %3, 0;\n\t"
        "mov.u64 %0, 0;\n\t"
        "mov.u32 %1, 0;\n\t"
        "mov.u32 %2, 0;\n\t"
        "@p  ld.global.nc.u64 %0, [%4];\n\t"
        "@!p ld.global.nc.u32 %1, [%5];\n\t"
        "@!p ld.global.nc.u32 %2, [%6];\n\t"
        "}"
        : "=l"(hp), "=r"(ua), "=r"(ub)
        : "r"(pr), "l"(ph), "l"(pa), "l"(pb));
    uint32_t wa, wb;
    if (pr) {
        const uint32_t lo = (uint32_t)hp;          // entry a&~1 (even)
        const uint32_t hi = (uint32_t)(hp >> 32);  // entry a|1  (odd)
        const bool odd = (a & 1u) != 0u;
        wa = odd ? hi : lo;
        wb = odd ? lo : hi;
    } else {
        wa = ua;
        wb = ub;
    }
    ea = __half22float2(*(const __half2*)&wa);
    eb = __half22float2(*(const __half2*)&wb);
}

__global__ __launch_bounds__(BLOCK, 7)
void hash_encode_kernel(const float* __restrict__ inputs,
                        float4* __restrict__ out,
                        int npts)
{
    __shared__ float s_in[PTS_PER_BLK * 3];
    __shared__ float s_scale[NLEV];

    const int tid = threadIdx.x;
    {
        int gidx = blockIdx.x * (PTS_PER_BLK * 3) + tid;
        if (tid < PTS_PER_BLK * 3 && gidx < npts * 3)
            s_in[tid] = inputs[gidx];
        if (tid < NLEV)
            s_scale[tid] = g_scales[tid];
    }
    __syncthreads();

    const int p = tid >> 3;       // point within block (0..31)
    const int s = tid & 7;        // sub-thread: handles levels 2s, 2s+1
    const long long point = (long long)blockIdx.x * PTS_PER_BLK + p;
    if (point >= npts) return;

    const float x = s_in[p * 3 + 0];
    const float y = s_in[p * 3 + 1];
    const float z = s_in[p * 3 + 2];

    float4 r;

    #pragma unroll
    for (int i = 0; i < 2; ++i) {
        const int l = (s << 1) + i;
        const float scale  = s_scale[l];
        const uint32_t res = c_res[l];

        // pos = x*scale + 0.5, NO fma contraction (floor must match reference).
        const float posx = __fadd_rn(__fmul_rn(x, scale), 0.5f);
        const float posy = __fadd_rn(__fmul_rn(y, scale), 0.5f);
        const float posz = __fadd_rn(__fmul_rn(z, scale), 0.5f);
        const float fx = floorf(posx), fy = floorf(posy), fz = floorf(posz);
        const float tx = posx - fx,  ty = posy - fy,  tz = posz - fz;
        const uint32_t gx = (uint32_t)fx, gy = (uint32_t)fy, gz = (uint32_t)fz;
        const uint32_t rm1 = res - 1u;
        const uint32_t x0 = min(gx,      rm1), x1 = min(gx + 1u, rm1);
        const uint32_t y0 = min(gy,      rm1), y1 = min(gy + 1u, rm1);
        const uint32_t z0 = min(gz,      rm1), z1 = min(gz + 1u, rm1);

        // 4 x-pairs; pair q has (y,z) bits (q&1, q>>1).
        float2 ea[4], eb[4];
        if (l >= 5) {
            const uint32_t* __restrict__ tabh = g_half + c_off[l];
            const uint32_t hy0 = y0 * 2654435761u, hy1 = y1 * 2654435761u;
            const uint32_t hz0 = z0 * 805459861u,  hz1 = z1 * 805459861u;
            const uint32_t m = 0x7FFFFu;
            uint32_t ia[4], ib[4];
            ia[0] = (x0 ^ hy0 ^ hz0) & m;  ib[0] = (x1 ^ hy0 ^ hz0) & m;
            ia[1] = (x0 ^ hy1 ^ hz0) & m;  ib[1] = (x1 ^ hy1 ^ hz0) & m;
            ia[2] = (x0 ^ hy0 ^ hz1) & m;  ib[2] = (x1 ^ hy0 ^ hz1) & m;
            ia[3] = (x0 ^ hy1 ^ hz1) & m;  ib[3] = (x1 ^ hy1 ^ hz1) & m;
            #pragma unroll
            for (int q = 0; q < 4; ++q)
                pair_gather(tabh, ia[q], ib[q], ea[q], eb[q]);
        } else {
            // Dense: dup table makes every x-pair exactly one aligned 8B load.
            const unsigned long long* __restrict__ dup = g_dup + c_off[l];
            const bool bsame = (x1 == x0);
            const uint32_t r2  = res * res;
            const uint32_t by0 = y0 * res, by1 = y1 * res;
            const uint32_t bz0 = z0 * r2,  bz1 = z1 * r2;
            uint32_t ia[4];
            ia[0] = x0 + by0 + bz0;
            ia[1] = x0 + by1 + bz0;
            ia[2] = x0 + by0 + bz1;
            ia[3] = x0 + by1 + bz1;
            #pragma unroll
            for (int q = 0; q < 4; ++q) {
                const unsigned long long v = __ldg(dup + ia[q]);
                const uint32_t lo = (uint32_t)v;           // entry ia
                const uint32_t hi = (uint32_t)(v >> 32);   // entry ia+1
                const uint32_t wb = bsame ? lo : hi;
                ea[q] = __half22float2(*(const __half2*)&lo);
                eb[q] = __half22float2(*(const __half2*)&wb);
            }
        }

        const float wx0 = 1.0f - tx, wy0 = 1.0f - ty, wz0 = 1.0f - tz;
        float a0 = 0.0f, a1 = 0.0f;
        #pragma unroll
        for (int q = 0; q < 4; ++q) {
            const float wy = (q & 1) ? ty : wy0;
            const float wz = (q & 2) ? tz : wz0;
            const float wyz = __fmul_rn(wy, wz);
            const float wa  = __fmul_rn(wx0, wyz);
            const float wb  = __fmul_rn(tx,  wyz);
            a0 = fmaf(wa, ea[q].x, a0);
            a1 = fmaf(wa, ea[q].y, a1);
            a0 = fmaf(wb, eb[q].x, a0);
            a1 = fmaf(wb, eb[q].y, a1);
        }
        if (i == 0) { r.x = a0; r.y = a1; }
        else        { r.z = a0; r.w = a1; }
    }

    // Warp = 4 points x 8 subthreads -> 512B contiguous store, fully coalesced.
    out[point * 8 + s] = r;
}

extern "C" void kernel_launch(void* const* d_in, const int* in_sizes, int n_in,
                              void* d_out, int out_size)
{
    const float*  inputs = (const float*)d_in[0];
    const float2* emb    = (const float2*)d_in[1];
    float4*       out    = (float4*)d_out;

    const int npts = in_sizes[0] / 3;

    const int setup_n = (HASH_PARAMS / 2 > DENSE_PARAMS) ? HASH_PARAMS / 2
                                                         : DENSE_PARAMS;
    setup_kernel<<<(setup_n + 255) / 256, 256>>>(emb);

    const int total_threads = npts * 8;
    const int nblocks = (total_threads + BLOCK - 1) / BLOCK;
    hash_encode_kernel<<<nblocks, BLOCK>>>(inputs, out, npts);
}

// round 15
// speedup vs baseline: 1.3889x; 1.1336x over previous
#include <cuda_runtime.h>
#include <cuda_fp16.h>
#include <stdint.h>

// ---------------------------------------------------------------------------
// HashEncoder (Instant-NGP multires hash grid): B=2097152 pts, D=3, L=16, C=2
// base_res=16, desired=2048, log2_hashmap=19.
//
// res : 16 23 31 43 59 | 81 112 154 213 295 407 562 777 1073 1483 2048
// l<5 dense (res^3 aligned to 8), l>=5 hashed with hmap = 2^19.
//
// R13 = R12 (proven optimum for hash levels: fp16 shadow, plain ld.global.nc,
// paired x-duo = one aligned 8B load else two 4B) + dense QUAD table:
//   g_quad[i] = fp16x2 of (h[x,y,z], h[x1c,y,z], h[x,y1c,z], h[x1c,y1c,z])
//   with clamping baked in at build time. Dense levels: 2 x LDG.128 per level
//   (z0/z1 planes) instead of 4 x 8B. Decisive test of scattered-LDG.128
//   wavefront cost (1 vs 2 wf/lane): -10% if 1, neutral if 2.
// ---------------------------------------------------------------------------

#define NLEV 16
#define BLOCK 256
#define PTS_PER_BLK 32            // 8 threads per point, 2 levels per thread
#define TOTAL_PARAMS 6098120
#define DENSE_PARAMS 330952       // OFFSETS[5]
#define HASH_PARAMS (TOTAL_PARAMS - DENSE_PARAMS)   // 11 * 2^19

__constant__ uint32_t c_res[NLEV] = {
    16u, 23u, 31u, 43u, 59u, 81u, 112u, 154u,
    213u, 295u, 407u, 562u, 777u, 1073u, 1483u, 2048u
};
__constant__ uint32_t c_off[NLEV] = {
    0u, 4096u, 16264u, 46056u, 125568u, 330952u, 855240u, 1379528u,
    1903816u, 2428104u, 2952392u, 3476680u, 4000968u, 4525256u, 5049544u, 5573832u
};

__device__ float g_scales[NLEV];
// fp16x2 shadow (one uint32 per entry); only the hash region is read.
__device__ __align__(128) uint32_t g_half[TOTAL_PARAMS];
// Dense quad table: per entry the 4 (x,y)-corner values of its cell, clamped.
__device__ __align__(128) uint4 g_quad[DENSE_PARAMS];

__device__ __forceinline__ uint32_t f2h(float2 e) {
    __half2 h = __floats2half2_rn(e.x, e.y);
    return *(uint32_t*)&h;
}

// One setup kernel: scales + dense quad + hash-region fp16 shadow.
__global__ __launch_bounds__(256)
void setup_kernel(const float2* __restrict__ emb) {
    if (blockIdx.x == 0 && threadIdx.x < NLEV) {
        double s = exp2((double)threadIdx.x * (7.0 / 15.0)) * 16.0 - 1.0;
        g_scales[threadIdx.x] = (float)s;
    }
    const int gi = blockIdx.x * blockDim.x + threadIdx.x;

    // Dense quad: decompose gi -> (level, x, y, z); bake x/y clamping.
    if (gi < DENSE_PARAMS) {
        int l = 0;
        #pragma unroll
        for (int k = 1; k < 5; ++k)
            if ((uint32_t)gi >= c_off[k]) l = k;
        const uint32_t res = c_res[l];
        const uint32_t off = c_off[l];
        const uint32_t li  = (uint32_t)gi - off;
        const uint32_t r2  = res * res;
        if (li < r2 * res) {                      // skip align-to-8 padding
            const uint32_t x = li % res;
            const uint32_t rem = li / res;
            const uint32_t y = rem % res;
            const uint32_t x1 = min(x + 1u, res - 1u);
            const uint32_t y1 = min(y + 1u, res - 1u);
            const uint32_t b  = (uint32_t)gi - x - y * res;  // (0, y=0) of row-block
            uint4 q;
            q.x = f2h(emb[b + x  + y  * res]);
            q.y = f2h(emb[b + x1 + y  * res]);
            q.z = f2h(emb[b + x  + y1 * res]);
            q.w = f2h(emb[b + x1 + y1 * res]);
            g_quad[gi] = q;
        } else {
            g_quad[gi] = make_uint4(0u, 0u, 0u, 0u);
        }
    }
    // Hash region fp16 shadow: pair i covers entries DENSE_PARAMS+2i, +2i+1.
    if (gi < HASH_PARAMS / 2) {
        const int base = DENSE_PARAMS + 2 * gi;
        const float4 e = *(const float4*)(emb + base);
        const uint32_t w0 = f2h(make_float2(e.x, e.y));
        const uint32_t w1 = f2h(make_float2(e.z, e.w));
        *(uint64_t*)&g_half[base] = ((uint64_t)w1 << 32) | w0;
    }
}

// Hash-level pair-gather: if b == a^1 (~50%), one aligned 8B load fetches both
// corners; else two 4B loads. True predication, outputs pre-zeroed.
__device__ __forceinline__ void pair_gather(const uint32_t* __restrict__ tabh,
                                            uint32_t a, uint32_t b,
                                            float2& ea, float2& eb)
{
    const unsigned pr = (b == (a ^ 1u)) ? 1u : 0u;
    const uint32_t* ph = tabh + (a & ~1u);   // 8B-aligned (offsets all even)
    const uint32_t* pa = tabh + a;
    const uint32_t* pb = tabh + b;
    unsigned long long hp;
    uint32_t ua, ub;
    asm volatile(
        "{\n\t"
        ".reg .pred p;\n\t"
        "setp.ne.u32 p, %3, 0;\n\t"
        "mov.u64 %0, 0;\n\t"
        "mov.u32 %1, 0;\n\t"
        "mov.u32 %2, 0;\n\t"
        "@p  ld.global.nc.u64 %0, [%4];\n\t"
        "@!p ld.global.nc.u32 %1, [%5];\n\t"
        "@!p ld.global.nc.u32 %2, [%6];\n\t"
        "}"
        : "=l"(hp), "=r"(ua), "=r"(ub)
        : "r"(pr), "l"(ph), "l"(pa), "l"(pb));
    uint32_t wa, wb;
    if (pr) {
        const uint32_t lo = (uint32_t)hp;          // entry a&~1 (even)
        const uint32_t hi = (uint32_t)(hp >> 32);  // entry a|1  (odd)
        const bool odd = (a & 1u) != 0u;
        wa = odd ? hi : lo;
        wb = odd ? lo : hi;
    } else {
        wa = ua;
        wb = ub;
    }
    ea = __half22float2(*(const __half2*)&wa);
    eb = __half22float2(*(const __half2*)&wb);
}

__global__ __launch_bounds__(BLOCK, 7)
void hash_encode_kernel(const float* __restrict__ inputs,
                        float4* __restrict__ out,
                        int npts)
{
    __shared__ float s_in[PTS_PER_BLK * 3];
    __shared__ float s_scale[NLEV];

    const int tid = threadIdx.x;
    {
        int gidx = blockIdx.x * (PTS_PER_BLK * 3) + tid;
        if (tid < PTS_PER_BLK * 3 && gidx < npts * 3)
            s_in[tid] = inputs[gidx];
        if (tid < NLEV)
            s_scale[tid] = g_scales[tid];
    }
    __syncthreads();

    const int p = tid >> 3;       // point within block (0..31)
    const int s = tid & 7;        // sub-thread: handles levels 2s, 2s+1
    const long long point = (long long)blockIdx.x * PTS_PER_BLK + p;
    if (point >= npts) return;

    const float x = s_in[p * 3 + 0];
    const float y = s_in[p * 3 + 1];
    const float z = s_in[p * 3 + 2];

    float4 r;

    #pragma unroll
    for (int i = 0; i < 2; ++i) {
        const int l = (s << 1) + i;
        const float scale  = s_scale[l];
        const uint32_t res = c_res[l];

        // pos = x*scale + 0.5, NO fma contraction (floor must match reference).
        const float posx = __fadd_rn(__fmul_rn(x, scale), 0.5f);
        const float posy = __fadd_rn(__fmul_rn(y, scale), 0.5f);
        const float posz = __fadd_rn(__fmul_rn(z, scale), 0.5f);
        const float fx = floorf(posx), fy = floorf(posy), fz = floorf(posz);
        const float tx = posx - fx,  ty = posy - fy,  tz = posz - fz;
        const uint32_t gx = (uint32_t)fx, gy = (uint32_t)fy, gz = (uint32_t)fz;
        const uint32_t rm1 = res - 1u;
        const uint32_t x0 = min(gx,      rm1), x1 = min(gx + 1u, rm1);
        const uint32_t y0 = min(gy,      rm1), y1 = min(gy + 1u, rm1);
        const uint32_t z0 = min(gz,      rm1), z1 = min(gz + 1u, rm1);

        const float wx0 = 1.0f - tx, wy0 = 1.0f - ty, wz0 = 1.0f - tz;
        float a0 = 0.0f, a1 = 0.0f;

        if (l >= 5) {
            const uint32_t* __restrict__ tabh = g_half + c_off[l];
            const uint32_t hy0 = y0 * 2654435761u, hy1 = y1 * 2654435761u;
            const uint32_t hz0 = z0 * 805459861u,  hz1 = z1 * 805459861u;
            const uint32_t m = 0x7FFFFu;
            uint32_t ia[4], ib[4];
            ia[0] = (x0 ^ hy0 ^ hz0) & m;  ib[0] = (x1 ^ hy0 ^ hz0) & m;
            ia[1] = (x0 ^ hy1 ^ hz0) & m;  ib[1] = (x1 ^ hy1 ^ hz0) & m;
            ia[2] = (x0 ^ hy0 ^ hz1) & m;  ib[2] = (x1 ^ hy0 ^ hz1) & m;
            ia[3] = (x0 ^ hy1 ^ hz1) & m;  ib[3] = (x1 ^ hy1 ^ hz1) & m;
            float2 ea[4], eb[4];
            #pragma unroll
            for (int q = 0; q < 4; ++q)
                pair_gather(tabh, ia[q], ib[q], ea[q], eb[q]);
            #pragma unroll
            for (int q = 0; q < 4; ++q) {
                const float wy = (q & 1) ? ty : wy0;
                const float wz = (q & 2) ? tz : wz0;
                const float wyz = __fmul_rn(wy, wz);
                const float wa  = __fmul_rn(wx0, wyz);
                const float wb  = __fmul_rn(tx,  wyz);
                a0 = fmaf(wa, ea[q].x, a0);
                a1 = fmaf(wa, ea[q].y, a1);
                a0 = fmaf(wb, eb[q].x, a0);
                a1 = fmaf(wb, eb[q].y, a1);
            }
        } else {
            // Dense quad: one LDG.128 per z-plane; clamping baked at build.
            const uint4* __restrict__ quad = g_quad + c_off[l];
            const uint32_t r2 = res * res;
            const uint32_t base = x0 + y0 * res;
            const uint4 v0 = __ldg(quad + base + z0 * r2);
            const uint4 v1 = __ldg(quad + base + z1 * r2);
            const float2 e00a = __half22float2(*(const __half2*)&v0.x);
            const float2 e10a = __half22float2(*(const __half2*)&v0.y);
            const float2 e01a = __half22float2(*(const __half2*)&v0.z);
            const float2 e11a = __half22float2(*(const __half2*)&v0.w);
            const float2 e00b = __half22float2(*(const __half2*)&v1.x);
            const float2 e10b = __half22float2(*(const __half2*)&v1.y);
            const float2 e01b = __half22float2(*(const __half2*)&v1.z);
            const float2 e11b = __half22float2(*(const __half2*)&v1.w);
            const float w00a = __fmul_rn(__fmul_rn(wx0, wy0), wz0);
            const float w10a = __fmul_rn(__fmul_rn(tx,  wy0), wz0);
            const float w01a = __fmul_rn(__fmul_rn(wx0, ty),  wz0);
            const float w11a = __fmul_rn(__fmul_rn(tx,  ty),  wz0);
            const float w00b = __fmul_rn(__fmul_rn(wx0, wy0), tz);
            const float w10b = __fmul_rn(__fmul_rn(tx,  wy0), tz);
            const float w01b = __fmul_rn(__fmul_rn(wx0, ty),  tz);
            const float w11b = __fmul_rn(__fmul_rn(tx,  ty),  tz);
            a0 = fmaf(w00a, e00a.x, a0);  a1 = fmaf(w00a, e00a.y, a1);
            a0 = fmaf(w10a, e10a.x, a0);  a1 = fmaf(w10a, e10a.y, a1);
            a0 = fmaf(w01a, e01a.x, a0);  a1 = fmaf(w01a, e01a.y, a1);
            a0 = fmaf(w11a, e11a.x, a0);  a1 = fmaf(w11a, e11a.y, a1);
            a0 = fmaf(w00b, e00b.x, a0);  a1 = fmaf(w00b, e00b.y, a1);
            a0 = fmaf(w10b, e10b.x, a0);  a1 = fmaf(w10b, e10b.y, a1);
            a0 = fmaf(w01b, e01b.x, a0);  a1 = fmaf(w01b, e01b.y, a1);
            a0 = fmaf(w11b, e11b.x, a0);  a1 = fmaf(w11b, e11b.y, a1);
        }
        if (i == 0) { r.x = a0; r.y = a1; }
        else        { r.z = a0; r.w = a1; }
    }

    // Warp = 4 points x 8 subthreads -> 512B contiguous store, fully coalesced.
    out[point * 8 + s] = r;
}

extern "C" void kernel_launch(void* const* d_in, const int* in_sizes, int n_in,
                              void* d_out, int out_size)
{
    const float*  inputs = (const float*)d_in[0];
    const float2* emb    = (const float2*)d_in[1];
    float4*       out    = (float4*)d_out;

    const int npts = in_sizes[0] / 3;

    const int setup_n = (HASH_PARAMS / 2 > DENSE_PARAMS) ? HASH_PARAMS / 2
                                                         : DENSE_PARAMS;
    setup_kernel<<<(setup_n + 255) / 256, 256>>>(emb);

    const int total_threads = npts * 8;
    const int nblocks = (total_threads + BLOCK - 1) / BLOCK;
    hash_encode_kernel<<<nblocks, BLOCK>>>(inputs, out, npts);
}